// round 16
// baseline (speedup 1.0000x reference)
#include <cuda_runtime.h>
#include <cstdint>
#include <cstddef>

#define DEV_INLINE __device__ __forceinline__

// ---------------------------------------------------------------------------
// Shapes (fixed by setup_inputs)
// ---------------------------------------------------------------------------
static constexpr int B   = 128;
static constexpr int T   = 99;
static constexpr int DX  = 1024;
static constexpr int DZ  = 64;
static constexpr int DY  = 32;
static constexpr int DH  = 256;
static constexpr int DA  = 9;
static constexpr int HID = 512;
static constexpr int NSTEP = T - 1;      // 98
static constexpr int MROWS = B * T;      // 12672

// flattened output offsets (reference return tuple order)
static constexpr size_t O0  = 0;                                   // prior_y      (98,128,32,2)
static constexpr size_t O1  = O0  + (size_t)NSTEP * B * DY * 2;    // y_params_f   (98,128,32,2)
static constexpr size_t O2  = O1  + (size_t)NSTEP * B * DY * 2;    // ys_f         (98,128,32)
static constexpr size_t O3  = O2  + (size_t)NSTEP * B * DY;        // prior_z      (99,128,64,2)
static constexpr size_t O4  = O3  + (size_t)T * B * DZ * 2;        // z_params     (99,128,64,2)
static constexpr size_t O5  = O4  + (size_t)T * B * DZ * 2;        // zs           (99,128,64)
static constexpr size_t O6  = O5  + (size_t)T * B * DZ;            // xs_hat       (99,128,1024)
static constexpr size_t O7  = O6  + (size_t)T * B * DX;            // x_hat_params (99,128,1024,2)
static constexpr size_t O8  = O7  + (size_t)T * B * DX * 2;        // x_f          (99,128,1024)
static constexpr size_t O9  = O8  + (size_t)T * B * DX;            // hs_f         (98,128,256)
static constexpr size_t O10 = O9  + (size_t)NSTEP * B * DH;        // cs_f         (98,128,256)

static constexpr float LOG_STD = -2.30258509f;   // float32(log(0.1))

// ---------------------------------------------------------------------------
// Scratch (no allocation allowed -> __device__ globals)
// ---------------------------------------------------------------------------
__device__ float g_h1[(size_t)MROWS * HID];           // 25.9 MB
__device__ float g_h2[(size_t)MROWS * HID];           // 25.9 MB
__device__ float g_zm[(size_t)T * B * 2 * DZ];        // zm_params, layout (t,b,128)

// ---------------------------------------------------------------------------
// JAX threefry-2x32 (partitionable counters) + XLA erfinv (f32)
// ---------------------------------------------------------------------------
__host__ __device__ inline void threefry2x32(uint32_t k0, uint32_t k1,
                                             uint32_t x0, uint32_t x1,
                                             uint32_t& o0, uint32_t& o1)
{
    uint32_t ks0 = k0, ks1 = k1, ks2 = k0 ^ k1 ^ 0x1BD11BDAu;
    x0 += ks0; x1 += ks1;
#define TF_ROT(v,d) (((v) << (d)) | ((v) >> (32 - (d))))
#define TF_RND(r)  { x0 += x1; x1 = TF_ROT(x1, r); x1 ^= x0; }
    TF_RND(13) TF_RND(15) TF_RND(26) TF_RND(6)  x0 += ks1; x1 += ks2 + 1u;
    TF_RND(17) TF_RND(29) TF_RND(16) TF_RND(24) x0 += ks2; x1 += ks0 + 2u;
    TF_RND(13) TF_RND(15) TF_RND(26) TF_RND(6)  x0 += ks0; x1 += ks1 + 3u;
    TF_RND(17) TF_RND(29) TF_RND(16) TF_RND(24) x0 += ks1; x1 += ks2 + 4u;
    TF_RND(13) TF_RND(15) TF_RND(26) TF_RND(6)  x0 += ks2; x1 += ks0 + 5u;
#undef TF_RND
#undef TF_ROT
    o0 = x0; o1 = x1;
}

DEV_INLINE float erfinv_xla(float x)
{
    float w = -log1pf(-x * x);
    float p;
    if (w < 5.0f) {
        w = w - 2.5f;
        p = 2.81022636e-08f;
        p = fmaf(p, w, 3.43273939e-07f);
        p = fmaf(p, w, -3.5233877e-06f);
        p = fmaf(p, w, -4.39150654e-06f);
        p = fmaf(p, w, 0.00021858087f);
        p = fmaf(p, w, -0.00125372503f);
        p = fmaf(p, w, -0.00417768164f);
        p = fmaf(p, w, 0.246640727f);
        p = fmaf(p, w, 1.50140941f);
    } else {
        w = sqrtf(w) - 3.0f;
        p = -0.000200214257f;
        p = fmaf(p, w, 0.000100950558f);
        p = fmaf(p, w, 0.00134934322f);
        p = fmaf(p, w, -0.00367342844f);
        p = fmaf(p, w, 0.00573950773f);
        p = fmaf(p, w, -0.0076224613f);
        p = fmaf(p, w, 0.00943887047f);
        p = fmaf(p, w, 1.00167406f);
        p = fmaf(p, w, 2.83297682f);
    }
    return p * x;
}

// jax.random.normal(key, ...)[flat index i], 32-bit partitionable path
DEV_INLINE float jax_normal(uint32_t ka, uint32_t kb, uint32_t idx)
{
    uint32_t o0, o1;
    threefry2x32(ka, kb, 0u, idx, o0, o1);
    uint32_t bits = o0 ^ o1;
    float f = __uint_as_float((bits >> 9) | 0x3f800000u) - 1.0f;  // [0,1)
    const float LO = -0.99999994f;                                // nextafter(-1,0)
    float uu = fmaxf(LO, f * 2.0f + LO);
    return 1.41421356f * erfinv_xla(uu);
}

DEV_INLINE float sigmoidf_(float x) { return 1.0f / (1.0f + expf(-x)); }

// ---------------------------------------------------------------------------
// GEMM: C[M,N] = act(A[M,K] @ W[K,N] + bias)
// 128x128 tile, 256 threads, 8x8 microtile, K-step 8.
// mode 0: store to C (optional relu)
// mode 1: encoder-final -> g_zm transposed ((b,t) rows -> (t,b) layout)
// mode 2: decoder-final -> fused xs_hat / x_hat_params with inline threefry
// M = gridDim.y*128, N = gridDim.x*128 exactly; K % 8 == 0.
// ---------------------------------------------------------------------------
__global__ void __launch_bounds__(256, 2)
gemm_kernel(const float* __restrict__ A, const float* __restrict__ W,
            const float* __restrict__ bias, float* __restrict__ C,
            int N, int K, int relu, int mode,
            float* __restrict__ outb, uint32_t ka, uint32_t kb)
{
    __shared__ float As[8][128];
    __shared__ float Bs[8][128];
    const int tid  = threadIdx.x;
    const int tx   = tid & 15;
    const int ty   = tid >> 4;
    const int row0 = blockIdx.y * 128;
    const int col0 = blockIdx.x * 128;

    float acc[8][8];
#pragma unroll
    for (int i = 0; i < 8; i++)
#pragma unroll
        for (int j = 0; j < 8; j++) acc[i][j] = 0.0f;

    const int arow = tid >> 1;
    const int akk  = (tid & 1) << 2;
    const int brow = tid >> 5;
    const int bcol = (tid & 31) << 2;

    const float* aptr = A + (size_t)(row0 + arow) * K + akk;
    const float* bptr = W + (size_t)brow * N + col0 + bcol;

    for (int k0 = 0; k0 < K; k0 += 8) {
        float4 a4 = *(const float4*)(aptr + k0);
        float4 b4 = *(const float4*)(bptr + (size_t)k0 * N);
        As[akk + 0][arow] = a4.x;
        As[akk + 1][arow] = a4.y;
        As[akk + 2][arow] = a4.z;
        As[akk + 3][arow] = a4.w;
        *(float4*)&Bs[brow][bcol] = b4;
        __syncthreads();
#pragma unroll
        for (int kk = 0; kk < 8; kk++) {
            float a[8], bv[8];
            *(float4*)&a[0]  = *(const float4*)&As[kk][ty * 8];
            *(float4*)&a[4]  = *(const float4*)&As[kk][ty * 8 + 4];
            *(float4*)&bv[0] = *(const float4*)&Bs[kk][tx * 8];
            *(float4*)&bv[4] = *(const float4*)&Bs[kk][tx * 8 + 4];
#pragma unroll
            for (int i = 0; i < 8; i++)
#pragma unroll
                for (int j = 0; j < 8; j++)
                    acc[i][j] = fmaf(a[i], bv[j], acc[i][j]);
        }
        __syncthreads();
    }

#pragma unroll
    for (int i = 0; i < 8; i++) {
        const int m = row0 + ty * 8 + i;
#pragma unroll
        for (int j = 0; j < 8; j++) {
            const int col = col0 + tx * 8 + j;
            float v = acc[i][j] + bias[col];
            if (relu) v = fmaxf(v, 0.0f);
            if (mode == 0) {
                C[(size_t)m * N + col] = v;
            } else if (mode == 1) {
                const int tt = m % T;
                const int bb = m / T;
                g_zm[((size_t)tt * B + bb) * 128 + col] = v;
            } else {
                const size_t idx = (size_t)m * 1024 + col;
                const float eps = jax_normal(ka, kb, (uint32_t)idx);
                outb[O6 + idx]         = v + 0.1f * eps;
                outb[O7 + 2 * idx]     = v;
                outb[O7 + 2 * idx + 1] = LOG_STD;
            }
        }
    }
}

// ---------------------------------------------------------------------------
// Scan kernel: 64 CTAs x 256 threads, 2 batch rows per CTA, 98 steps.
// Weight loads shared between the two rows in registers (halves L2 traffic).
// ---------------------------------------------------------------------------
__global__ void __launch_bounds__(256)
scan_kernel(const float* __restrict__ u,
            const float* __restrict__ Wih, const float* __restrict__ Whh,
            const float* __restrict__ bih, const float* __restrict__ bhh,
            const float* __restrict__ Wy,  const float* __restrict__ by,
            const float* __restrict__ tW1, const float* __restrict__ tb1,
            const float* __restrict__ tW2, const float* __restrict__ tb2,
            const float* __restrict__ tW3, const float* __restrict__ tb3,
            float* __restrict__ out,
            uint32_t k0a, uint32_t k0b,
            uint32_t k1a, uint32_t k1b,
            uint32_t k2a, uint32_t k2b)
{
    __shared__ float sh[2][DH];
    __shared__ float sc[2][DH];
    __shared__ float szs[2][DZ];
    __shared__ float gates[2][4 * DH];
    __shared__ float xin[2][80];        // [zs(64), u_t(9)]
    __shared__ float in105[2][112];     // [zs(64), u_{t+1}(9), ys(32)]
    __shared__ float hid1[2][HID];
    __shared__ float hid2[2][HID];
    __shared__ float yv[2][2 * DY];
    __shared__ float ztr[2][2 * DZ];

    const int tid = threadIdx.x;
    const int b0  = blockIdx.x * 2;

    // init carries: h=c=0, zs0 = sample(zm[0], eps_z0)
    sh[0][tid] = 0.0f; sh[1][tid] = 0.0f;
    sc[0][tid] = 0.0f; sc[1][tid] = 0.0f;
    if (tid < 128) {
        const int r = tid >> 6, d = tid & 63, b = b0 + r;
        const float mu = g_zm[(size_t)b * 128 + 2 * d];
        const float ls = g_zm[(size_t)b * 128 + 2 * d + 1];
        szs[r][d] = mu + expf(ls) * jax_normal(k0a, k0b, (uint32_t)(b * DZ + d));
    }
    __syncthreads();

    for (int s = 0; s < NSTEP; s++) {
        // ---- inputs for this step -------------------------------------
        if (tid < 146) {
            const int r = tid / 73;
            const int k = tid - r * 73;
            const int b = b0 + r;
            const float v = (k < 64) ? szs[r][k]
                                     : u[((size_t)b * T + s) * DA + (k - 64)];
            xin[r][k] = v;
            in105[r][k] = (k < 64) ? v
                                   : u[((size_t)b * T + s + 1) * DA + (k - 64)];
        }
        __syncthreads();

        // ---- LSTM gates: 1024 outputs/row, 4 per thread ---------------
        {
            const int j0 = tid * 4;
            const float4 bi = *(const float4*)&bih[j0];
            const float4 bh = *(const float4*)&bhh[j0];
            float a0x = bi.x + bh.x, a0y = bi.y + bh.y, a0z = bi.z + bh.z, a0w = bi.w + bh.w;
            float a1x = a0x, a1y = a0y, a1z = a0z, a1w = a0w;
#pragma unroll 1
            for (int k = 0; k < 73; k++) {
                const float4 w = *(const float4*)&Wih[(size_t)k * 1024 + j0];
                const float x0 = xin[0][k], x1 = xin[1][k];
                a0x = fmaf(x0, w.x, a0x); a0y = fmaf(x0, w.y, a0y);
                a0z = fmaf(x0, w.z, a0z); a0w = fmaf(x0, w.w, a0w);
                a1x = fmaf(x1, w.x, a1x); a1y = fmaf(x1, w.y, a1y);
                a1z = fmaf(x1, w.z, a1z); a1w = fmaf(x1, w.w, a1w);
            }
#pragma unroll 8
            for (int k = 0; k < DH; k++) {
                const float4 w = *(const float4*)&Whh[(size_t)k * 1024 + j0];
                const float h0 = sh[0][k], h1 = sh[1][k];
                a0x = fmaf(h0, w.x, a0x); a0y = fmaf(h0, w.y, a0y);
                a0z = fmaf(h0, w.z, a0z); a0w = fmaf(h0, w.w, a0w);
                a1x = fmaf(h1, w.x, a1x); a1y = fmaf(h1, w.y, a1y);
                a1z = fmaf(h1, w.z, a1z); a1w = fmaf(h1, w.w, a1w);
            }
            gates[0][j0] = a0x; gates[0][j0 + 1] = a0y;
            gates[0][j0 + 2] = a0z; gates[0][j0 + 3] = a0w;
            gates[1][j0] = a1x; gates[1][j0 + 1] = a1y;
            gates[1][j0 + 2] = a1z; gates[1][j0 + 3] = a1w;
        }
        __syncthreads();

        // ---- LSTM state update + hs_f/cs_f outputs --------------------
        {
            const int n = tid;
#pragma unroll
            for (int r = 0; r < 2; r++) {
                const int b = b0 + r;
                const float gi = gates[r][n];
                const float gf = gates[r][DH + n];
                const float gg = gates[r][2 * DH + n];
                const float go = gates[r][3 * DH + n];
                const float c_old = sc[r][n], h_old = sh[r][n];
                out[O9  + ((size_t)s * B + b) * DH + n] = h_old;
                out[O10 + ((size_t)s * B + b) * DH + n] = c_old;
                const float c1 = sigmoidf_(gf) * c_old + sigmoidf_(gi) * tanhf(gg);
                const float h1 = sigmoidf_(go) * tanhf(c1);
                sc[r][n] = c1; sh[r][n] = h1;
            }
        }
        __syncthreads();

        // ---- y head: 64 outputs/row ------------------------------------
        if (tid < 128) {
            const int r = tid >> 6, j = tid & 63;
            float a = by[j];
#pragma unroll 8
            for (int k = 0; k < DH; k++)
                a = fmaf(sh[r][k], Wy[(size_t)k * 64 + j], a);
            yv[r][j] = a;
        }
        __syncthreads();

        // ---- sample y, write y outputs --------------------------------
        if (tid < 64) {
            const int r = tid >> 5, d = tid & 31, b = b0 + r;
            const float mu = yv[r][2 * d];
            const float ls = yv[r][2 * d + 1];
            const float eps = jax_normal(k1a, k1b, (uint32_t)((s * B + b) * DY + d));
            const float ys = mu + expf(ls) * eps;
            const size_t o = ((size_t)s * B + b) * DY + d;
            out[O1 + 2 * o]     = mu;
            out[O1 + 2 * o + 1] = ls;
            out[O2 + o]         = ys;
            in105[r][73 + d] = ys;
        }
        __syncthreads();

        // ---- transition MLP L1 (105 -> 512, relu) ---------------------
        {
            const int j0 = tid * 2;
            const float bb0 = tb1[j0], bb1 = tb1[j0 + 1];
            float a00 = bb0, a01 = bb1, a10 = bb0, a11 = bb1;
#pragma unroll 1
            for (int k = 0; k < 105; k++) {
                const float2 w = *(const float2*)&tW1[(size_t)k * HID + j0];
                const float x0 = in105[0][k], x1 = in105[1][k];
                a00 = fmaf(x0, w.x, a00); a01 = fmaf(x0, w.y, a01);
                a10 = fmaf(x1, w.x, a10); a11 = fmaf(x1, w.y, a11);
            }
            hid1[0][j0] = fmaxf(a00, 0.0f); hid1[0][j0 + 1] = fmaxf(a01, 0.0f);
            hid1[1][j0] = fmaxf(a10, 0.0f); hid1[1][j0 + 1] = fmaxf(a11, 0.0f);
        }
        __syncthreads();

        // ---- transition MLP L2 (512 -> 512, relu) ---------------------
        {
            const int j0 = tid * 2;
            const float bb0 = tb2[j0], bb1 = tb2[j0 + 1];
            float a00 = bb0, a01 = bb1, a10 = bb0, a11 = bb1;
#pragma unroll 8
            for (int k = 0; k < HID; k++) {
                const float2 w = *(const float2*)&tW2[(size_t)k * HID + j0];
                const float x0 = hid1[0][k], x1 = hid1[1][k];
                a00 = fmaf(x0, w.x, a00); a01 = fmaf(x0, w.y, a01);
                a10 = fmaf(x1, w.x, a10); a11 = fmaf(x1, w.y, a11);
            }
            hid2[0][j0] = fmaxf(a00, 0.0f); hid2[0][j0 + 1] = fmaxf(a01, 0.0f);
            hid2[1][j0] = fmaxf(a10, 0.0f); hid2[1][j0 + 1] = fmaxf(a11, 0.0f);
        }
        __syncthreads();

        // ---- transition MLP L3 (512 -> 128) ---------------------------
        {
            const int r = tid >> 7, j = tid & 127;
            float a = tb3[j];
#pragma unroll 8
            for (int k = 0; k < HID; k++)
                a = fmaf(hid2[r][k], tW3[(size_t)k * 128 + j], a);
            ztr[r][j] = a;
        }
        __syncthreads();

        // ---- Bayes fusion + sample z ----------------------------------
        if (tid < 128) {
            const int r = tid >> 6, d = tid & 63, b = b0 + r;
            const float mu1 = ztr[r][2 * d], ls1 = ztr[r][2 * d + 1];
            const size_t zmo = ((size_t)(s + 1) * B + b) * 128;
            const float mu2 = g_zm[zmo + 2 * d], ls2 = g_zm[zmo + 2 * d + 1];
            const float p1 = expf(-2.0f * ls1);
            const float p2 = expf(-2.0f * ls2);
            const float var = 1.0f / (p1 + p2);
            const float mu = var * (mu1 * p1 + mu2 * p2);
            const float lv = 0.5f * logf(var);
            const float eps = jax_normal(k2a, k2b, (uint32_t)((s * B + b) * DZ + d));
            const float z1 = mu + expf(lv) * eps;
            const size_t o = ((size_t)(s + 1) * B + b) * DZ + d;
            out[O4 + 2 * o]     = mu;
            out[O4 + 2 * o + 1] = lv;
            out[O5 + o]         = z1;
            szs[r][d] = z1;
        }
        __syncthreads();
    }
}

// ---------------------------------------------------------------------------
// Small elementwise kernels
// ---------------------------------------------------------------------------
__global__ void z0_kernel(float* __restrict__ out, uint32_t ka, uint32_t kb)
{
    const int i = blockIdx.x * 256 + threadIdx.x;   // 16384 threads
    if (i < B * 2 * DZ) out[O4 + i] = g_zm[i];
    if (i < B * DZ) {
        const int b = i >> 6, d = i & 63;
        const float mu = g_zm[(size_t)b * 128 + 2 * d];
        const float ls = g_zm[(size_t)b * 128 + 2 * d + 1];
        out[O5 + i] = mu + expf(ls) * jax_normal(ka, kb, (uint32_t)i);
    }
}

__global__ void priorz_kernel(float* __restrict__ out)
{
    const int i = blockIdx.x * 256 + threadIdx.x;
    const int n = T * B * 2 * DZ;
    if (i >= n) return;
    out[O3 + i] = (i < B * 2 * DZ) ? 0.0f : out[O4 + i - B * 2 * DZ];
}

__global__ void prior_y_kernel(const float* __restrict__ emb,
                               const int* __restrict__ labels,
                               float* __restrict__ out)
{
    const int i = blockIdx.x * 256 + threadIdx.x;
    if (i >= NSTEP * B * DY) return;
    const int d = i & 31;
    const int b = (i >> 5) & 127;
    const int obj = labels[b * 3] + labels[b * 3 + 1] + labels[b * 3 + 2];
    const float v = tanhf(emb[obj * DY + d]);
    out[O0 + 2 * (size_t)i]     = v;
    out[O0 + 2 * (size_t)i + 1] = LOG_STD;
}

__global__ void xf_kernel(const float* __restrict__ x, float* __restrict__ out)
{
    const int i = blockIdx.x * 256 + threadIdx.x;
    if (i >= T * B * DX) return;
    const int k = i & 1023;
    const int b = (i >> 10) & 127;
    const int t = i >> 17;
    out[O8 + i] = x[((size_t)b * T + t) * DX + k];
}

// ---------------------------------------------------------------------------
// Launch
// ---------------------------------------------------------------------------
extern "C" void kernel_launch(void* const* d_in, const int* in_sizes, int n_in,
                              void* d_out, int out_size)
{
    const float* x      = (const float*)d_in[0];
    const float* u      = (const float*)d_in[1];
    const int*   labels = (const int*)d_in[2];
    // 'H' may or may not be materialized as a scalar input; detect it.
    int base = 3;
    if (n_in > 3 && in_sizes[3] == 1) base = 4;
    const float* emb = (const float*)d_in[base + 0];
    const float* eW1 = (const float*)d_in[base + 1];
    const float* eb1 = (const float*)d_in[base + 2];
    const float* eW2 = (const float*)d_in[base + 3];
    const float* eb2 = (const float*)d_in[base + 4];
    const float* eW3 = (const float*)d_in[base + 5];
    const float* eb3 = (const float*)d_in[base + 6];
    const float* dW1 = (const float*)d_in[base + 7];
    const float* db1 = (const float*)d_in[base + 8];
    const float* dW2 = (const float*)d_in[base + 9];
    const float* db2 = (const float*)d_in[base + 10];
    const float* dW3 = (const float*)d_in[base + 11];
    const float* db3 = (const float*)d_in[base + 12];
    const float* Wih = (const float*)d_in[base + 13];
    const float* Whh = (const float*)d_in[base + 14];
    const float* bih = (const float*)d_in[base + 15];
    const float* bhh = (const float*)d_in[base + 16];
    const float* Wy  = (const float*)d_in[base + 17];
    const float* by  = (const float*)d_in[base + 18];
    const float* tW1 = (const float*)d_in[base + 19];
    const float* tb1 = (const float*)d_in[base + 20];
    const float* tW2 = (const float*)d_in[base + 21];
    const float* tb2 = (const float*)d_in[base + 22];
    const float* tW3 = (const float*)d_in[base + 23];
    const float* tb3 = (const float*)d_in[base + 24];
    float* out = (float*)d_out;

    // subkeys: jax.random.split(key(42), 4)  (fold-like, partitionable)
    uint32_t sk[4][2];
    for (uint32_t i = 0; i < 4; i++)
        threefry2x32(0u, 42u, 0u, i, sk[i][0], sk[i][1]);

    float *h1p = nullptr, *h2p = nullptr;
    cudaGetSymbolAddress((void**)&h1p, g_h1);
    cudaGetSymbolAddress((void**)&h2p, g_h2);

    const dim3 blk(256);

    // encoder MLP (rows = b*T + t)
    gemm_kernel<<<dim3(4, 99), blk>>>(x,   eW1, eb1, h1p, 512, 1024, 1, 0, nullptr, 0u, 0u);
    gemm_kernel<<<dim3(4, 99), blk>>>(h1p, eW2, eb2, h2p, 512, 512,  1, 0, nullptr, 0u, 0u);
    gemm_kernel<<<dim3(1, 99), blk>>>(h2p, eW3, eb3, nullptr, 128, 512, 0, 1, nullptr, 0u, 0u);

    // z_params[0], zs[0]
    z0_kernel<<<64, blk>>>(out, sk[0][0], sk[0][1]);

    // 98-step scan
    scan_kernel<<<64, blk>>>(u, Wih, Whh, bih, bhh, Wy, by,
                             tW1, tb1, tW2, tb2, tW3, tb3, out,
                             sk[0][0], sk[0][1], sk[1][0], sk[1][1],
                             sk[2][0], sk[2][1]);

    // prior_z = [0, z_params[:-1]]
    priorz_kernel<<<(T * B * 2 * DZ + 255) / 256, blk>>>(out);

    // decoder MLP on zs (rows = t*B + b), final layer fused with eps_x
    gemm_kernel<<<dim3(4, 99), blk>>>(out + O5, dW1, db1, h1p, 512, 64, 1, 0, nullptr, 0u, 0u);
    gemm_kernel<<<dim3(4, 99), blk>>>(h1p, dW2, db2, h2p, 512, 512, 1, 0, nullptr, 0u, 0u);
    gemm_kernel<<<dim3(8, 99), blk>>>(h2p, dW3, db3, nullptr, 1024, 512, 0, 2,
                                      out, sk[3][0], sk[3][1]);

    // independent outputs
    prior_y_kernel<<<(NSTEP * B * DY + 255) / 256, blk>>>(emb, labels, out);
    xf_kernel<<<(T * B * DX + 255) / 256, blk>>>(x, out);
}

// round 17
// speedup vs baseline: 1.4115x; 1.4115x over previous
#include <cuda_runtime.h>
#include <cstdint>
#include <cstddef>

#define DEV_INLINE __device__ __forceinline__

// ---------------------------------------------------------------------------
// Shapes (fixed by setup_inputs)
// ---------------------------------------------------------------------------
static constexpr int B   = 128;
static constexpr int T   = 99;
static constexpr int DX  = 1024;
static constexpr int DZ  = 64;
static constexpr int DY  = 32;
static constexpr int DH  = 256;
static constexpr int DA  = 9;
static constexpr int HID = 512;
static constexpr int NSTEP = T - 1;      // 98
static constexpr int MROWS = B * T;      // 12672

// flattened output offsets (reference return tuple order)
static constexpr size_t O0  = 0;                                   // prior_y      (98,128,32,2)
static constexpr size_t O1  = O0  + (size_t)NSTEP * B * DY * 2;    // y_params_f   (98,128,32,2)
static constexpr size_t O2  = O1  + (size_t)NSTEP * B * DY * 2;    // ys_f         (98,128,32)
static constexpr size_t O3  = O2  + (size_t)NSTEP * B * DY;        // prior_z      (99,128,64,2)
static constexpr size_t O4  = O3  + (size_t)T * B * DZ * 2;        // z_params     (99,128,64,2)
static constexpr size_t O5  = O4  + (size_t)T * B * DZ * 2;        // zs           (99,128,64)
static constexpr size_t O6  = O5  + (size_t)T * B * DZ;            // xs_hat       (99,128,1024)
static constexpr size_t O7  = O6  + (size_t)T * B * DX;            // x_hat_params (99,128,1024,2)
static constexpr size_t O8  = O7  + (size_t)T * B * DX * 2;        // x_f          (99,128,1024)
static constexpr size_t O9  = O8  + (size_t)T * B * DX;            // hs_f         (98,128,256)
static constexpr size_t O10 = O9  + (size_t)NSTEP * B * DH;        // cs_f         (98,128,256)

static constexpr float LOG_STD = -2.30258509f;   // float32(log(0.1))

// ---------------------------------------------------------------------------
// Scratch (no allocation allowed -> __device__ globals)
// ---------------------------------------------------------------------------
__device__ float g_h1[(size_t)MROWS * HID];           // 25.9 MB
__device__ float g_h2[(size_t)MROWS * HID];           // 25.9 MB
__device__ float g_zm[(size_t)T * B * 2 * DZ];        // zm_params, layout (t,b,128)

// ---------------------------------------------------------------------------
// JAX threefry-2x32 (partitionable counters) + XLA erfinv (f32)
// ---------------------------------------------------------------------------
__host__ __device__ inline void threefry2x32(uint32_t k0, uint32_t k1,
                                             uint32_t x0, uint32_t x1,
                                             uint32_t& o0, uint32_t& o1)
{
    uint32_t ks0 = k0, ks1 = k1, ks2 = k0 ^ k1 ^ 0x1BD11BDAu;
    x0 += ks0; x1 += ks1;
#define TF_ROT(v,d) (((v) << (d)) | ((v) >> (32 - (d))))
#define TF_RND(r)  { x0 += x1; x1 = TF_ROT(x1, r); x1 ^= x0; }
    TF_RND(13) TF_RND(15) TF_RND(26) TF_RND(6)  x0 += ks1; x1 += ks2 + 1u;
    TF_RND(17) TF_RND(29) TF_RND(16) TF_RND(24) x0 += ks2; x1 += ks0 + 2u;
    TF_RND(13) TF_RND(15) TF_RND(26) TF_RND(6)  x0 += ks0; x1 += ks1 + 3u;
    TF_RND(17) TF_RND(29) TF_RND(16) TF_RND(24) x0 += ks1; x1 += ks2 + 4u;
    TF_RND(13) TF_RND(15) TF_RND(26) TF_RND(6)  x0 += ks2; x1 += ks0 + 5u;
#undef TF_RND
#undef TF_ROT
    o0 = x0; o1 = x1;
}

DEV_INLINE float erfinv_xla(float x)
{
    float w = -log1pf(-x * x);
    float p;
    if (w < 5.0f) {
        w = w - 2.5f;
        p = 2.81022636e-08f;
        p = fmaf(p, w, 3.43273939e-07f);
        p = fmaf(p, w, -3.5233877e-06f);
        p = fmaf(p, w, -4.39150654e-06f);
        p = fmaf(p, w, 0.00021858087f);
        p = fmaf(p, w, -0.00125372503f);
        p = fmaf(p, w, -0.00417768164f);
        p = fmaf(p, w, 0.246640727f);
        p = fmaf(p, w, 1.50140941f);
    } else {
        w = sqrtf(w) - 3.0f;
        p = -0.000200214257f;
        p = fmaf(p, w, 0.000100950558f);
        p = fmaf(p, w, 0.00134934322f);
        p = fmaf(p, w, -0.00367342844f);
        p = fmaf(p, w, 0.00573950773f);
        p = fmaf(p, w, -0.0076224613f);
        p = fmaf(p, w, 0.00943887047f);
        p = fmaf(p, w, 1.00167406f);
        p = fmaf(p, w, 2.83297682f);
    }
    return p * x;
}

DEV_INLINE float jax_normal(uint32_t ka, uint32_t kb, uint32_t idx)
{
    uint32_t o0, o1;
    threefry2x32(ka, kb, 0u, idx, o0, o1);
    uint32_t bits = o0 ^ o1;
    float f = __uint_as_float((bits >> 9) | 0x3f800000u) - 1.0f;  // [0,1)
    const float LO = -0.99999994f;                                // nextafter(-1,0)
    float uu = fmaxf(LO, f * 2.0f + LO);
    return 1.41421356f * erfinv_xla(uu);
}

DEV_INLINE float sigmoidf_(float x) { return 1.0f / (1.0f + expf(-x)); }

// ---------------------------------------------------------------------------
// GEMM: C[M,N] = act(A[M,K] @ W[K,N] + bias)
// 128x128 tile, 256 threads, 8x8 microtile, K-step 8, double-buffered smem
// with register prefetch.
// mode 0: store to C (optional relu)
// mode 1: encoder-final -> g_zm transposed ((b,t) rows -> (t,b) layout)
// mode 2: decoder-final -> fused xs_hat / x_hat_params with inline threefry
// ---------------------------------------------------------------------------
__global__ void __launch_bounds__(256, 2)
gemm_kernel(const float* __restrict__ A, const float* __restrict__ W,
            const float* __restrict__ bias, float* __restrict__ C,
            int N, int K, int relu, int mode,
            float* __restrict__ outb, uint32_t ka, uint32_t kb)
{
    __shared__ float As[2][8][128];
    __shared__ float Bs[2][8][128];
    const int tid  = threadIdx.x;
    const int tx   = tid & 15;
    const int ty   = tid >> 4;
    const int row0 = blockIdx.y * 128;
    const int col0 = blockIdx.x * 128;

    float acc[8][8];
#pragma unroll
    for (int i = 0; i < 8; i++)
#pragma unroll
        for (int j = 0; j < 8; j++) acc[i][j] = 0.0f;

    const int arow = tid >> 1;
    const int akk  = (tid & 1) << 2;
    const int brow = tid >> 5;
    const int bcol = (tid & 31) << 2;

    const float* aptr = A + (size_t)(row0 + arow) * K + akk;
    const float* bptr = W + (size_t)brow * N + col0 + bcol;

    const int NB = K >> 3;

    float4 a4 = *(const float4*)(aptr);
    float4 b4 = *(const float4*)(bptr);
    As[0][akk + 0][arow] = a4.x;
    As[0][akk + 1][arow] = a4.y;
    As[0][akk + 2][arow] = a4.z;
    As[0][akk + 3][arow] = a4.w;
    *(float4*)&Bs[0][brow][bcol] = b4;
    __syncthreads();

    int buf = 0;
    for (int kb2 = 0; kb2 < NB; kb2++) {
        if (kb2 + 1 < NB) {
            a4 = *(const float4*)(aptr + (kb2 + 1) * 8);
            b4 = *(const float4*)(bptr + (size_t)(kb2 + 1) * 8 * N);
        }
#pragma unroll
        for (int kk = 0; kk < 8; kk++) {
            float a[8], bv[8];
            *(float4*)&a[0]  = *(const float4*)&As[buf][kk][ty * 8];
            *(float4*)&a[4]  = *(const float4*)&As[buf][kk][ty * 8 + 4];
            *(float4*)&bv[0] = *(const float4*)&Bs[buf][kk][tx * 8];
            *(float4*)&bv[4] = *(const float4*)&Bs[buf][kk][tx * 8 + 4];
#pragma unroll
            for (int i = 0; i < 8; i++)
#pragma unroll
                for (int j = 0; j < 8; j++)
                    acc[i][j] = fmaf(a[i], bv[j], acc[i][j]);
        }
        if (kb2 + 1 < NB) {
            const int nb = buf ^ 1;
            As[nb][akk + 0][arow] = a4.x;
            As[nb][akk + 1][arow] = a4.y;
            As[nb][akk + 2][arow] = a4.z;
            As[nb][akk + 3][arow] = a4.w;
            *(float4*)&Bs[nb][brow][bcol] = b4;
        }
        __syncthreads();
        buf ^= 1;
    }

#pragma unroll
    for (int i = 0; i < 8; i++) {
        const int m = row0 + ty * 8 + i;
#pragma unroll
        for (int j = 0; j < 8; j++) {
            const int col = col0 + tx * 8 + j;
            float v = acc[i][j] + bias[col];
            if (relu) v = fmaxf(v, 0.0f);
            if (mode == 0) {
                C[(size_t)m * N + col] = v;
            } else if (mode == 1) {
                const int tt = m % T;
                const int bb = m / T;
                g_zm[((size_t)tt * B + bb) * 128 + col] = v;
            } else {
                const size_t idx = (size_t)m * 1024 + col;
                const float eps = jax_normal(ka, kb, (uint32_t)idx);
                outb[O6 + idx]         = v + 0.1f * eps;
                outb[O7 + 2 * idx]     = v;
                outb[O7 + 2 * idx + 1] = LOG_STD;
            }
        }
    }
}

// ---------------------------------------------------------------------------
// Scan kernel: 64 CTAs x 256 threads, 2 batch rows per CTA, 98 steps.
// Activations for the two rows interleaved as float2 in shared memory so one
// LDS.64 feeds both rows' FMAs; weight loads are shared between the two rows
// in registers. All short dot-product loops fully unrolled for MLP.
// ---------------------------------------------------------------------------
__global__ void __launch_bounds__(256)
scan_kernel(const float* __restrict__ u,
            const float* __restrict__ Wih, const float* __restrict__ Whh,
            const float* __restrict__ bih, const float* __restrict__ bhh,
            const float* __restrict__ Wy,  const float* __restrict__ by,
            const float* __restrict__ tW1, const float* __restrict__ tb1,
            const float* __restrict__ tW2, const float* __restrict__ tb2,
            const float* __restrict__ tW3, const float* __restrict__ tb3,
            float* __restrict__ out,
            uint32_t k0a, uint32_t k0b,
            uint32_t k1a, uint32_t k1b,
            uint32_t k2a, uint32_t k2b)
{
    __shared__ float2 sh2[DH];          // h for rows 0,1
    __shared__ float2 sc2[DH];          // c for rows 0,1
    __shared__ float2 szs2[DZ];         // zs for rows 0,1
    __shared__ float  gates[2][4 * DH];
    __shared__ float2 xin2[73];         // [zs(64), u_t(9)]
    __shared__ float2 in105_2[105];     // [zs(64), u_{t+1}(9), ys(32)]
    __shared__ float2 hid1_2[HID];
    __shared__ float2 hid2_2[HID];
    __shared__ float  yv[2][2 * DY];
    __shared__ float  ztr[2][2 * DZ];

    const int tid = threadIdx.x;
    const int b0  = blockIdx.x * 2;

    sh2[tid] = make_float2(0.0f, 0.0f);
    sc2[tid] = make_float2(0.0f, 0.0f);
    if (tid < 128) {
        const int r = tid >> 6, d = tid & 63, b = b0 + r;
        const float mu = g_zm[(size_t)b * 128 + 2 * d];
        const float ls = g_zm[(size_t)b * 128 + 2 * d + 1];
        ((float*)szs2)[2 * d + r] =
            mu + expf(ls) * jax_normal(k0a, k0b, (uint32_t)(b * DZ + d));
    }
    __syncthreads();

    for (int s = 0; s < NSTEP; s++) {
        // ---- inputs for this step -------------------------------------
        if (tid < 73) {
            float2 v, w;
            if (tid < 64) {
                v = szs2[tid];
                w = v;
            } else {
                const int k = tid - 64;
                v.x = u[((size_t)(b0 + 0) * T + s) * DA + k];
                v.y = u[((size_t)(b0 + 1) * T + s) * DA + k];
                w.x = u[((size_t)(b0 + 0) * T + s + 1) * DA + k];
                w.y = u[((size_t)(b0 + 1) * T + s + 1) * DA + k];
            }
            xin2[tid]    = v;
            in105_2[tid] = w;
        }
        __syncthreads();

        // ---- LSTM gates: 1024 outputs/row, 4 per thread ---------------
        {
            const int j0 = tid * 4;
            const float4 bi = *(const float4*)&bih[j0];
            const float4 bh = *(const float4*)&bhh[j0];
            float a0x = bi.x + bh.x, a0y = bi.y + bh.y, a0z = bi.z + bh.z, a0w = bi.w + bh.w;
            float a1x = a0x, a1y = a0y, a1z = a0z, a1w = a0w;
#pragma unroll
            for (int k = 0; k < 73; k++) {
                const float4 w = *(const float4*)&Wih[(size_t)k * 1024 + j0];
                const float2 xv = xin2[k];
                a0x = fmaf(xv.x, w.x, a0x); a0y = fmaf(xv.x, w.y, a0y);
                a0z = fmaf(xv.x, w.z, a0z); a0w = fmaf(xv.x, w.w, a0w);
                a1x = fmaf(xv.y, w.x, a1x); a1y = fmaf(xv.y, w.y, a1y);
                a1z = fmaf(xv.y, w.z, a1z); a1w = fmaf(xv.y, w.w, a1w);
            }
#pragma unroll 16
            for (int k = 0; k < DH; k++) {
                const float4 w = *(const float4*)&Whh[(size_t)k * 1024 + j0];
                const float2 hv = sh2[k];
                a0x = fmaf(hv.x, w.x, a0x); a0y = fmaf(hv.x, w.y, a0y);
                a0z = fmaf(hv.x, w.z, a0z); a0w = fmaf(hv.x, w.w, a0w);
                a1x = fmaf(hv.y, w.x, a1x); a1y = fmaf(hv.y, w.y, a1y);
                a1z = fmaf(hv.y, w.z, a1z); a1w = fmaf(hv.y, w.w, a1w);
            }
            *(float4*)&gates[0][j0] = make_float4(a0x, a0y, a0z, a0w);
            *(float4*)&gates[1][j0] = make_float4(a1x, a1y, a1z, a1w);
        }
        __syncthreads();

        // ---- LSTM state update + hs_f/cs_f outputs --------------------
        {
            const int n = tid;
            const float2 c_old = sc2[n];
            const float2 h_old = sh2[n];
            out[O9  + ((size_t)s * B + b0) * DH + n]       = h_old.x;
            out[O9  + ((size_t)s * B + b0 + 1) * DH + n]   = h_old.y;
            out[O10 + ((size_t)s * B + b0) * DH + n]       = c_old.x;
            out[O10 + ((size_t)s * B + b0 + 1) * DH + n]   = c_old.y;
            float2 c1, h1;
            {
                const float gi = gates[0][n], gf = gates[0][DH + n];
                const float gg = gates[0][2 * DH + n], go = gates[0][3 * DH + n];
                c1.x = sigmoidf_(gf) * c_old.x + sigmoidf_(gi) * tanhf(gg);
                h1.x = sigmoidf_(go) * tanhf(c1.x);
            }
            {
                const float gi = gates[1][n], gf = gates[1][DH + n];
                const float gg = gates[1][2 * DH + n], go = gates[1][3 * DH + n];
                c1.y = sigmoidf_(gf) * c_old.y + sigmoidf_(gi) * tanhf(gg);
                h1.y = sigmoidf_(go) * tanhf(c1.y);
            }
            sc2[n] = c1;
            sh2[n] = h1;
        }
        __syncthreads();

        // ---- y head: 64 outputs/row -----------------------------------
        if (tid < 128) {
            const int j = tid & 63;
            float a0 = by[j], a1 = a0;
            if (tid < 64) {
#pragma unroll 16
                for (int k = 0; k < DH; k++)
                    a0 = fmaf(sh2[k].x, Wy[(size_t)k * 64 + j], a0);
                yv[0][j] = a0;
            } else {
#pragma unroll 16
                for (int k = 0; k < DH; k++)
                    a1 = fmaf(sh2[k].y, Wy[(size_t)k * 64 + j], a1);
                yv[1][j] = a1;
            }
        }
        __syncthreads();

        // ---- sample y, write y outputs --------------------------------
        if (tid < 64) {
            const int r = tid >> 5, d = tid & 31, b = b0 + r;
            const float mu = yv[r][2 * d];
            const float ls = yv[r][2 * d + 1];
            const float eps = jax_normal(k1a, k1b, (uint32_t)((s * B + b) * DY + d));
            const float ys = mu + expf(ls) * eps;
            const size_t o = ((size_t)s * B + b) * DY + d;
            out[O1 + 2 * o]     = mu;
            out[O1 + 2 * o + 1] = ls;
            out[O2 + o]         = ys;
            ((float*)in105_2)[2 * (73 + d) + r] = ys;
        }
        __syncthreads();

        // ---- transition MLP L1 (105 -> 512, relu) ---------------------
        {
            const int j0 = tid * 2;
            const float bb0 = tb1[j0], bb1 = tb1[j0 + 1];
            float a00 = bb0, a01 = bb1, a10 = bb0, a11 = bb1;
#pragma unroll
            for (int k = 0; k < 105; k++) {
                const float2 w = *(const float2*)&tW1[(size_t)k * HID + j0];
                const float2 xv = in105_2[k];
                a00 = fmaf(xv.x, w.x, a00); a01 = fmaf(xv.x, w.y, a01);
                a10 = fmaf(xv.y, w.x, a10); a11 = fmaf(xv.y, w.y, a11);
            }
            hid1_2[j0]     = make_float2(fmaxf(a00, 0.0f), fmaxf(a10, 0.0f));
            hid1_2[j0 + 1] = make_float2(fmaxf(a01, 0.0f), fmaxf(a11, 0.0f));
        }
        __syncthreads();

        // ---- transition MLP L2 (512 -> 512, relu) ---------------------
        {
            const int j0 = tid * 2;
            const float bb0 = tb2[j0], bb1 = tb2[j0 + 1];
            float a00 = bb0, a01 = bb1, a10 = bb0, a11 = bb1;
#pragma unroll 16
            for (int k = 0; k < HID; k++) {
                const float2 w = *(const float2*)&tW2[(size_t)k * HID + j0];
                const float2 xv = hid1_2[k];
                a00 = fmaf(xv.x, w.x, a00); a01 = fmaf(xv.x, w.y, a01);
                a10 = fmaf(xv.y, w.x, a10); a11 = fmaf(xv.y, w.y, a11);
            }
            hid2_2[j0]     = make_float2(fmaxf(a00, 0.0f), fmaxf(a10, 0.0f));
            hid2_2[j0 + 1] = make_float2(fmaxf(a01, 0.0f), fmaxf(a11, 0.0f));
        }
        __syncthreads();

        // ---- transition MLP L3 (512 -> 128) ---------------------------
        {
            const int r = tid >> 7, j = tid & 127;
            float a = tb3[j];
            if (r == 0) {
#pragma unroll 16
                for (int k = 0; k < HID; k++)
                    a = fmaf(hid2_2[k].x, tW3[(size_t)k * 128 + j], a);
                ztr[0][j] = a;
            } else {
#pragma unroll 16
                for (int k = 0; k < HID; k++)
                    a = fmaf(hid2_2[k].y, tW3[(size_t)k * 128 + j], a);
                ztr[1][j] = a;
            }
        }
        __syncthreads();

        // ---- Bayes fusion + sample z ----------------------------------
        if (tid < 128) {
            const int r = tid >> 6, d = tid & 63, b = b0 + r;
            const float mu1 = ztr[r][2 * d], ls1 = ztr[r][2 * d + 1];
            const size_t zmo = ((size_t)(s + 1) * B + b) * 128;
            const float mu2 = g_zm[zmo + 2 * d], ls2 = g_zm[zmo + 2 * d + 1];
            const float p1 = expf(-2.0f * ls1);
            const float p2 = expf(-2.0f * ls2);
            const float var = 1.0f / (p1 + p2);
            const float mu = var * (mu1 * p1 + mu2 * p2);
            const float lv = 0.5f * logf(var);
            const float eps = jax_normal(k2a, k2b, (uint32_t)((s * B + b) * DZ + d));
            const float z1 = mu + expf(lv) * eps;
            const size_t o = ((size_t)(s + 1) * B + b) * DZ + d;
            out[O4 + 2 * o]     = mu;
            out[O4 + 2 * o + 1] = lv;
            out[O5 + o]         = z1;
            ((float*)szs2)[2 * d + r] = z1;
        }
        __syncthreads();
    }
}

// ---------------------------------------------------------------------------
// Small elementwise kernels
// ---------------------------------------------------------------------------
__global__ void z0_kernel(float* __restrict__ out, uint32_t ka, uint32_t kb)
{
    const int i = blockIdx.x * 256 + threadIdx.x;   // 16384 threads
    if (i < B * 2 * DZ) out[O4 + i] = g_zm[i];
    if (i < B * DZ) {
        const int b = i >> 6, d = i & 63;
        const float mu = g_zm[(size_t)b * 128 + 2 * d];
        const float ls = g_zm[(size_t)b * 128 + 2 * d + 1];
        out[O5 + i] = mu + expf(ls) * jax_normal(ka, kb, (uint32_t)i);
    }
}

__global__ void priorz_kernel(float* __restrict__ out)
{
    const int i = blockIdx.x * 256 + threadIdx.x;
    const int n = T * B * 2 * DZ;
    if (i >= n) return;
    out[O3 + i] = (i < B * 2 * DZ) ? 0.0f : out[O4 + i - B * 2 * DZ];
}

__global__ void prior_y_kernel(const float* __restrict__ emb,
                               const int* __restrict__ labels,
                               float* __restrict__ out)
{
    const int i = blockIdx.x * 256 + threadIdx.x;
    if (i >= NSTEP * B * DY) return;
    const int d = i & 31;
    const int b = (i >> 5) & 127;
    const int obj = labels[b * 3] + labels[b * 3 + 1] + labels[b * 3 + 2];
    const float v = tanhf(emb[obj * DY + d]);
    out[O0 + 2 * (size_t)i]     = v;
    out[O0 + 2 * (size_t)i + 1] = LOG_STD;
}

__global__ void xf_kernel(const float* __restrict__ x, float* __restrict__ out)
{
    const int i = blockIdx.x * 256 + threadIdx.x;
    if (i >= T * B * DX) return;
    const int k = i & 1023;
    const int b = (i >> 10) & 127;
    const int t = i >> 17;
    out[O8 + i] = x[((size_t)b * T + t) * DX + k];
}

// ---------------------------------------------------------------------------
// Launch
// ---------------------------------------------------------------------------
extern "C" void kernel_launch(void* const* d_in, const int* in_sizes, int n_in,
                              void* d_out, int out_size)
{
    const float* x      = (const float*)d_in[0];
    const float* u      = (const float*)d_in[1];
    const int*   labels = (const int*)d_in[2];
    int base = 3;
    if (n_in > 3 && in_sizes[3] == 1) base = 4;
    const float* emb = (const float*)d_in[base + 0];
    const float* eW1 = (const float*)d_in[base + 1];
    const float* eb1 = (const float*)d_in[base + 2];
    const float* eW2 = (const float*)d_in[base + 3];
    const float* eb2 = (const float*)d_in[base + 4];
    const float* eW3 = (const float*)d_in[base + 5];
    const float* eb3 = (const float*)d_in[base + 6];
    const float* dW1 = (const float*)d_in[base + 7];
    const float* db1 = (const float*)d_in[base + 8];
    const float* dW2 = (const float*)d_in[base + 9];
    const float* db2 = (const float*)d_in[base + 10];
    const float* dW3 = (const float*)d_in[base + 11];
    const float* db3 = (const float*)d_in[base + 12];
    const float* Wih = (const float*)d_in[base + 13];
    const float* Whh = (const float*)d_in[base + 14];
    const float* bih = (const float*)d_in[base + 15];
    const float* bhh = (const float*)d_in[base + 16];
    const float* Wy  = (const float*)d_in[base + 17];
    const float* by  = (const float*)d_in[base + 18];
    const float* tW1 = (const float*)d_in[base + 19];
    const float* tb1 = (const float*)d_in[base + 20];
    const float* tW2 = (const float*)d_in[base + 21];
    const float* tb2 = (const float*)d_in[base + 22];
    const float* tW3 = (const float*)d_in[base + 23];
    const float* tb3 = (const float*)d_in[base + 24];
    float* out = (float*)d_out;

    // subkeys: jax.random.split(key(42), 4)
    uint32_t sk[4][2];
    for (uint32_t i = 0; i < 4; i++)
        threefry2x32(0u, 42u, 0u, i, sk[i][0], sk[i][1]);

    float *h1p = nullptr, *h2p = nullptr;
    cudaGetSymbolAddress((void**)&h1p, g_h1);
    cudaGetSymbolAddress((void**)&h2p, g_h2);

    const dim3 blk(256);

    // encoder MLP (rows = b*T + t)
    gemm_kernel<<<dim3(4, 99), blk>>>(x,   eW1, eb1, h1p, 512, 1024, 1, 0, nullptr, 0u, 0u);
    gemm_kernel<<<dim3(4, 99), blk>>>(h1p, eW2, eb2, h2p, 512, 512,  1, 0, nullptr, 0u, 0u);
    gemm_kernel<<<dim3(1, 99), blk>>>(h2p, eW3, eb3, nullptr, 128, 512, 0, 1, nullptr, 0u, 0u);

    // 98-step scan (launch #4 — ncu capture slot)
    scan_kernel<<<64, blk>>>(u, Wih, Whh, bih, bhh, Wy, by,
                             tW1, tb1, tW2, tb2, tW3, tb3, out,
                             sk[0][0], sk[0][1], sk[1][0], sk[1][1],
                             sk[2][0], sk[2][1]);

    // z_params[0], zs[0]
    z0_kernel<<<64, blk>>>(out, sk[0][0], sk[0][1]);

    // prior_z = [0, z_params[:-1]]
    priorz_kernel<<<(T * B * 2 * DZ + 255) / 256, blk>>>(out);

    // decoder MLP on zs (rows = t*B + b), final layer fused with eps_x
    gemm_kernel<<<dim3(4, 99), blk>>>(out + O5, dW1, db1, h1p, 512, 64, 1, 0, nullptr, 0u, 0u);
    gemm_kernel<<<dim3(4, 99), blk>>>(h1p, dW2, db2, h2p, 512, 512, 1, 0, nullptr, 0u, 0u);
    gemm_kernel<<<dim3(8, 99), blk>>>(h2p, dW3, db3, nullptr, 1024, 512, 0, 2,
                                      out, sk[3][0], sk[3][1]);

    // independent outputs
    prior_y_kernel<<<(NSTEP * B * DY + 255) / 256, blk>>>(emb, labels, out);
    xf_kernel<<<(T * B * DX + 255) / 256, blk>>>(x, out);
}